// round 2
// baseline (speedup 1.0000x reference)
#include <cuda_runtime.h>
#include <cstdint>

#define NNODES  100000
#define HIDDIM  128
#define KIN     500
#define KCHEB   512
#define ODIM    16

// Scratch (device globals: allocation-free per harness rules)
static __device__ float g_h0[(size_t)NNODES * HIDDIM];   // 51.2 MB
static __device__ float g_h1[(size_t)NNODES * HIDDIM];   // 51.2 MB
static __device__ float g_C[2 * KCHEB * HIDDIM];         // reshaped cheb coeffs

// ---------------------------------------------------------------------------
// Reshape cheb_coeffs [2,128,128,4] (l,i,o,d) -> C[l][k=4i+d][o]  ([512,128])
// ---------------------------------------------------------------------------
__global__ void prep_coeffs_kernel(const float* __restrict__ cc) {
    int idx = blockIdx.x * blockDim.x + threadIdx.x;
    if (idx >= 2 * 128 * 128 * 4) return;
    int d = idx & 3;
    int o = (idx >> 2) & 127;
    int i = (idx >> 9) & 127;
    int l = idx >> 16;
    g_C[l * (KCHEB * HIDDIM) + (i * 4 + d) * HIDDIM + o] = cc[idx];
}

__global__ void zero_kernel(float* __restrict__ p, int n4) {
    int idx = blockIdx.x * blockDim.x + threadIdx.x;
    if (idx < n4) ((float4*)p)[idx] = make_float4(0.f, 0.f, 0.f, 0.f);
}

// ---------------------------------------------------------------------------
// Tiled fp32 GEMM: C[nRows,128] = A @ B.
//   CHEB=0: A is [nRows,K] row-major (x @ W_in path)
//   CHEB=1: A is h[nRows,128]; logical A[r, 4i+d] = T_d(tanh(h[r,i])), K=512.
//           Basis is generated on the fly during the smem A-tile fill.
// Block: 256 threads, tile 128 rows x 128 cols, K-step 8, 8x8 microtile.
// ---------------------------------------------------------------------------
template <int CHEB>
__global__ void __launch_bounds__(256) gemm_kernel(
    const float* __restrict__ A, const float* __restrict__ B,
    float* __restrict__ C, int nRows, int K)
{
    __shared__ float As[8][128];   // [k][row]
    __shared__ float Bs[8][128];   // [k][col]
    const int tid = threadIdx.x;
    const int tx  = tid & 15;      // col group
    const int ty  = tid >> 4;      // row group
    const int rowBase = blockIdx.x * 128;

    float acc[8][8];
#pragma unroll
    for (int r = 0; r < 8; r++)
#pragma unroll
        for (int c = 0; c < 8; c++) acc[r][c] = 0.f;

    for (int k0 = 0; k0 < K; k0 += 8) {
        // ---- A tile ----
        if (CHEB) {
            // 256 threads cover 128 rows x 2 h-columns -> 8 basis k-rows
            int rl = tid & 127;
            int ii = tid >> 7;                       // 0 or 1
            int rg = rowBase + rl; if (rg >= nRows) rg = nRows - 1;
            int ig = (k0 >> 2) + ii;                 // h column, < 128
            float t  = tanhf(A[(size_t)rg * HIDDIM + ig]);
            float T2 = fmaf(2.f * t, t, -1.f);
            float T3 = fmaf(2.f * t, T2, -t);
            As[ii * 4 + 0][rl] = 1.f;
            As[ii * 4 + 1][rl] = t;
            As[ii * 4 + 2][rl] = T2;
            As[ii * 4 + 3][rl] = T3;
        } else {
            int rl   = tid >> 1;
            int half = tid & 1;
            int rg = rowBase + rl; if (rg >= nRows) rg = nRows - 1;
            int kk = k0 + half * 4;
            float4 a = make_float4(0.f, 0.f, 0.f, 0.f);
            if (kk < K)                              // K%4==0 -> full vec or none
                a = *(const float4*)(A + (size_t)rg * K + kk);
            As[half * 4 + 0][rl] = a.x;
            As[half * 4 + 1][rl] = a.y;
            As[half * 4 + 2][rl] = a.z;
            As[half * 4 + 3][rl] = a.w;
        }
        // ---- B tile ----
        {
            int kb = tid >> 5;
            int cb = (tid & 31) << 2;
            float4 b = make_float4(0.f, 0.f, 0.f, 0.f);
            if (k0 + kb < K)
                b = *(const float4*)(B + (size_t)(k0 + kb) * HIDDIM + cb);
            *(float4*)&Bs[kb][cb] = b;
        }
        __syncthreads();

#pragma unroll
        for (int kk = 0; kk < 8; kk++) {
            float a[8], b[8];
            *(float4*)(a)     = *(const float4*)&As[kk][ty * 8];
            *(float4*)(a + 4) = *(const float4*)&As[kk][ty * 8 + 4];
            *(float4*)(b)     = *(const float4*)&Bs[kk][tx * 8];
            *(float4*)(b + 4) = *(const float4*)&Bs[kk][tx * 8 + 4];
#pragma unroll
            for (int r = 0; r < 8; r++)
#pragma unroll
                for (int c = 0; c < 8; c++)
                    acc[r][c] = fmaf(a[r], b[c], acc[r][c]);
        }
        __syncthreads();
    }

#pragma unroll
    for (int r = 0; r < 8; r++) {
        int rg = rowBase + ty * 8 + r;
        if (rg < nRows) {
            *(float4*)(C + (size_t)rg * HIDDIM + tx * 8) =
                make_float4(acc[r][0], acc[r][1], acc[r][2], acc[r][3]);
            *(float4*)(C + (size_t)rg * HIDDIM + tx * 8 + 4) =
                make_float4(acc[r][4], acc[r][5], acc[r][6], acc[r][7]);
        }
    }
}

// ---------------------------------------------------------------------------
// spmm: out[row] += h[col] per edge. Warp per edge, float4 gather, scalar REDs.
// Source/dest rows are L2-resident (51 MB each).
// ---------------------------------------------------------------------------
__global__ void spmm_kernel(const int* __restrict__ ei, int nE,
                            const float* __restrict__ hin,
                            float* __restrict__ hout)
{
    int idx = blockIdx.x * blockDim.x + threadIdx.x;
    int e = idx >> 5;
    if (e >= nE) return;
    int lane = idx & 31;
    int row = ei[e];
    int col = ei[nE + e];
    float4 v = *(const float4*)(hin + (size_t)col * HIDDIM + lane * 4);
    float* dst = hout + (size_t)row * HIDDIM + lane * 4;
    atomicAdd(dst + 0, v.x);
    atomicAdd(dst + 1, v.y);
    atomicAdd(dst + 2, v.z);
    atomicAdd(dst + 3, v.w);
}

// ---------------------------------------------------------------------------
// logits = h @ W_out, then log_softmax.  Warp per row.
// ---------------------------------------------------------------------------
__global__ void __launch_bounds__(256) out_kernel(
    const float* __restrict__ h, const float* __restrict__ Wout,
    float* __restrict__ out, int nRows)
{
    __shared__ float W[HIDDIM * ODIM];
    for (int i = threadIdx.x; i < HIDDIM * ODIM; i += 256) W[i] = Wout[i];
    __syncthreads();

    int gw = (blockIdx.x * 256 + threadIdx.x) >> 5;
    int lane = threadIdx.x & 31;
    if (gw >= nRows) return;

    float4 hv = *(const float4*)(h + (size_t)gw * HIDDIM + lane * 4);
    int i0 = lane * 4;
    float acc[ODIM];
#pragma unroll
    for (int o = 0; o < ODIM; o++) {
        float s = hv.x * W[(i0 + 0) * ODIM + o];
        s = fmaf(hv.y, W[(i0 + 1) * ODIM + o], s);
        s = fmaf(hv.z, W[(i0 + 2) * ODIM + o], s);
        s = fmaf(hv.w, W[(i0 + 3) * ODIM + o], s);
        acc[o] = s;
    }
#pragma unroll
    for (int off = 16; off > 0; off >>= 1)
#pragma unroll
        for (int o = 0; o < ODIM; o++)
            acc[o] += __shfl_xor_sync(0xffffffffu, acc[o], off);

    float m = acc[0];
#pragma unroll
    for (int o = 1; o < ODIM; o++) m = fmaxf(m, acc[o]);
    float s = 0.f;
#pragma unroll
    for (int o = 0; o < ODIM; o++) s += expf(acc[o] - m);
    float lse = m + logf(s);
    if (lane < ODIM) out[(size_t)gw * ODIM + lane] = acc[lane] - lse;
}

// ---------------------------------------------------------------------------
extern "C" void kernel_launch(void* const* d_in, const int* in_sizes, int n_in,
                              void* d_out, int out_size)
{
    const float* x    = (const float*)d_in[0];
    const int*   ei   = (const int*)d_in[1];
    const float* Win  = (const float*)d_in[2];
    const float* cc   = (const float*)d_in[3];
    const float* Wout = (const float*)d_in[4];
    float* out = (float*)d_out;

    const int nE    = in_sizes[1] / 2;
    const int nRows = NNODES;

    float *h0, *h1, *C;
    cudaGetSymbolAddress((void**)&h0, g_h0);
    cudaGetSymbolAddress((void**)&h1, g_h1);
    cudaGetSymbolAddress((void**)&C,  g_C);

    const int gemmBlocks = (nRows + 127) / 128;          // 782
    const int zero4      = nRows * (HIDDIM / 4);         // 3.2M float4
    const int zeroBlocks = (zero4 + 255) / 256;
    const int spmmBlocks = (nE * 32 + 255) / 256;

    prep_coeffs_kernel<<<512, 256>>>(cc);

    // h0 = x @ W_in
    gemm_kernel<0><<<gemmBlocks, 256>>>(x, Win, h0, nRows, KIN);

    // h1 = A h0
    zero_kernel<<<zeroBlocks, 256>>>(h1, zero4);
    spmm_kernel<<<spmmBlocks, 256>>>(ei, nE, h0, h1);

    // h0 = cheb(h1; C0)
    gemm_kernel<1><<<gemmBlocks, 256>>>(h1, C, h0, nRows, KCHEB);
    // h1 = A h0
    zero_kernel<<<zeroBlocks, 256>>>(h1, zero4);
    spmm_kernel<<<spmmBlocks, 256>>>(ei, nE, h0, h1);

    // h0 = cheb(h1; C1)
    gemm_kernel<1><<<gemmBlocks, 256>>>(h1, C + KCHEB * HIDDIM, h0, nRows, KCHEB);
    // h1 = A h0
    zero_kernel<<<zeroBlocks, 256>>>(h1, zero4);
    spmm_kernel<<<spmmBlocks, 256>>>(ei, nE, h0, h1);

    // out = log_softmax(h1 @ W_out)
    out_kernel<<<(nRows + 7) / 8, 256>>>(h1, Wout, out, nRows);
}

// round 3
// speedup vs baseline: 1.5844x; 1.5844x over previous
#include <cuda_runtime.h>
#include <cstdint>

#define NNODES  100000
#define HIDDIM  128
#define KIN     500
#define KCHEB   512
#define ODIM    16
#define MAXE    1600000

// Scratch (device globals: allocation-free per harness rules)
static __device__ float g_h0[(size_t)NNODES * HIDDIM];   // 51.2 MB
static __device__ float g_h1[(size_t)NNODES * HIDDIM];   // 51.2 MB
static __device__ float g_C[2 * KCHEB * HIDDIM];         // reshaped cheb coeffs
static __device__ int   g_deg[NNODES];
static __device__ int   g_rowStart[NNODES + 1];
static __device__ int   g_cursor[NNODES];
static __device__ int   g_colIdx[MAXE];                  // 6.4 MB

// ---------------------------------------------------------------------------
// Reshape cheb_coeffs [2,128,128,4] (l,i,o,d) -> C[l][k=4i+d][o]  ([512,128])
// ---------------------------------------------------------------------------
__global__ void prep_coeffs_kernel(const float* __restrict__ cc) {
    int idx = blockIdx.x * blockDim.x + threadIdx.x;
    if (idx >= 2 * 128 * 128 * 4) return;
    g_C[((idx >> 16) * KCHEB + ((idx >> 9) & 127) * 4 + (idx & 3)) * HIDDIM +
        ((idx >> 2) & 127)] = cc[idx];
}

// ---------------------------------------------------------------------------
// CSR build: degree histogram -> single-block scan -> scatter fill
// ---------------------------------------------------------------------------
__global__ void zero_deg_kernel(int* __restrict__ deg, int n) {
    int i = blockIdx.x * blockDim.x + threadIdx.x;
    if (i < n) deg[i] = 0;
}

__global__ void count_kernel(const int* __restrict__ ei, int nE,
                             int* __restrict__ deg) {
    int i = blockIdx.x * blockDim.x + threadIdx.x;
    if (i < nE) atomicAdd(&deg[ei[i]], 1);
}

// One block, 1024 threads: exclusive scan of deg[0..n) into rowStart & cursor.
__global__ void __launch_bounds__(1024) scan_kernel(
    const int* __restrict__ deg, int* __restrict__ rowStart,
    int* __restrict__ cursor, int n)
{
    __shared__ int s[1024];
    const int tid = threadIdx.x;
    const int CH = (n + 1023) / 1024;
    const int base = tid * CH;
    int sum = 0;
    for (int i = 0; i < CH; i++) {
        int j = base + i;
        if (j < n) sum += deg[j];
    }
    s[tid] = sum;
    __syncthreads();
    for (int off = 1; off < 1024; off <<= 1) {
        int v = (tid >= off) ? s[tid - off] : 0;
        __syncthreads();
        s[tid] += v;
        __syncthreads();
    }
    int run = (tid == 0) ? 0 : s[tid - 1];
    for (int i = 0; i < CH; i++) {
        int j = base + i;
        if (j < n) {
            rowStart[j] = run;
            cursor[j]   = run;
            run += deg[j];
        }
    }
    if (tid == 1023) rowStart[n] = run;
}

__global__ void fill_kernel(const int* __restrict__ ei, int nE,
                            int* __restrict__ cursor,
                            int* __restrict__ colIdx) {
    int i = blockIdx.x * blockDim.x + threadIdx.x;
    if (i >= nE) return;
    int row = ei[i];
    int col = ei[nE + i];
    int p = atomicAdd(&cursor[row], 1);
    colIdx[p] = col;
}

// ---------------------------------------------------------------------------
// spmm via CSR: warp per row, register accumulation, no atomics.
// ---------------------------------------------------------------------------
__global__ void __launch_bounds__(256) spmm_csr_kernel(
    const int* __restrict__ rowStart, const int* __restrict__ colIdx,
    const float* __restrict__ hin, float* __restrict__ hout, int n)
{
    int w = (blockIdx.x * 256 + threadIdx.x) >> 5;
    if (w >= n) return;
    int lane = threadIdx.x & 31;
    int s = rowStart[w];
    int e = rowStart[w + 1];

    float4 a0 = make_float4(0.f, 0.f, 0.f, 0.f);
    float4 a1 = make_float4(0.f, 0.f, 0.f, 0.f);
    int i = s;
    for (; i + 1 < e; i += 2) {
        int c0 = __ldg(&colIdx[i]);
        int c1 = __ldg(&colIdx[i + 1]);
        float4 v0 = *(const float4*)(hin + (size_t)c0 * HIDDIM + lane * 4);
        float4 v1 = *(const float4*)(hin + (size_t)c1 * HIDDIM + lane * 4);
        a0.x += v0.x; a0.y += v0.y; a0.z += v0.z; a0.w += v0.w;
        a1.x += v1.x; a1.y += v1.y; a1.z += v1.z; a1.w += v1.w;
    }
    if (i < e) {
        int c0 = __ldg(&colIdx[i]);
        float4 v0 = *(const float4*)(hin + (size_t)c0 * HIDDIM + lane * 4);
        a0.x += v0.x; a0.y += v0.y; a0.z += v0.z; a0.w += v0.w;
    }
    *(float4*)(hout + (size_t)w * HIDDIM + lane * 4) =
        make_float4(a0.x + a1.x, a0.y + a1.y, a0.z + a1.z, a0.w + a1.w);
}

// ---------------------------------------------------------------------------
// Tiled fp32 GEMM: C[nRows,128] = A @ B.  (unchanged from R2)
// ---------------------------------------------------------------------------
template <int CHEB>
__global__ void __launch_bounds__(256) gemm_kernel(
    const float* __restrict__ A, const float* __restrict__ B,
    float* __restrict__ C, int nRows, int K)
{
    __shared__ float As[8][128];
    __shared__ float Bs[8][128];
    const int tid = threadIdx.x;
    const int tx  = tid & 15;
    const int ty  = tid >> 4;
    const int rowBase = blockIdx.x * 128;

    float acc[8][8];
#pragma unroll
    for (int r = 0; r < 8; r++)
#pragma unroll
        for (int c = 0; c < 8; c++) acc[r][c] = 0.f;

    for (int k0 = 0; k0 < K; k0 += 8) {
        if (CHEB) {
            int rl = tid & 127;
            int ii = tid >> 7;
            int rg = rowBase + rl; if (rg >= nRows) rg = nRows - 1;
            int ig = (k0 >> 2) + ii;
            float t  = tanhf(A[(size_t)rg * HIDDIM + ig]);
            float T2 = fmaf(2.f * t, t, -1.f);
            float T3 = fmaf(2.f * t, T2, -t);
            As[ii * 4 + 0][rl] = 1.f;
            As[ii * 4 + 1][rl] = t;
            As[ii * 4 + 2][rl] = T2;
            As[ii * 4 + 3][rl] = T3;
        } else {
            int rl   = tid >> 1;
            int half = tid & 1;
            int rg = rowBase + rl; if (rg >= nRows) rg = nRows - 1;
            int kk = k0 + half * 4;
            float4 a = make_float4(0.f, 0.f, 0.f, 0.f);
            if (kk < K)
                a = *(const float4*)(A + (size_t)rg * K + kk);
            As[half * 4 + 0][rl] = a.x;
            As[half * 4 + 1][rl] = a.y;
            As[half * 4 + 2][rl] = a.z;
            As[half * 4 + 3][rl] = a.w;
        }
        {
            int kb = tid >> 5;
            int cb = (tid & 31) << 2;
            float4 b = make_float4(0.f, 0.f, 0.f, 0.f);
            if (k0 + kb < K)
                b = *(const float4*)(B + (size_t)(k0 + kb) * HIDDIM + cb);
            *(float4*)&Bs[kb][cb] = b;
        }
        __syncthreads();

#pragma unroll
        for (int kk = 0; kk < 8; kk++) {
            float a[8], b[8];
            *(float4*)(a)     = *(const float4*)&As[kk][ty * 8];
            *(float4*)(a + 4) = *(const float4*)&As[kk][ty * 8 + 4];
            *(float4*)(b)     = *(const float4*)&Bs[kk][tx * 8];
            *(float4*)(b + 4) = *(const float4*)&Bs[kk][tx * 8 + 4];
#pragma unroll
            for (int r = 0; r < 8; r++)
#pragma unroll
                for (int c = 0; c < 8; c++)
                    acc[r][c] = fmaf(a[r], b[c], acc[r][c]);
        }
        __syncthreads();
    }

#pragma unroll
    for (int r = 0; r < 8; r++) {
        int rg = rowBase + ty * 8 + r;
        if (rg < nRows) {
            *(float4*)(C + (size_t)rg * HIDDIM + tx * 8) =
                make_float4(acc[r][0], acc[r][1], acc[r][2], acc[r][3]);
            *(float4*)(C + (size_t)rg * HIDDIM + tx * 8 + 4) =
                make_float4(acc[r][4], acc[r][5], acc[r][6], acc[r][7]);
        }
    }
}

// ---------------------------------------------------------------------------
// logits = h @ W_out, then log_softmax.  Warp per row.
// ---------------------------------------------------------------------------
__global__ void __launch_bounds__(256) out_kernel(
    const float* __restrict__ h, const float* __restrict__ Wout,
    float* __restrict__ out, int nRows)
{
    __shared__ float W[HIDDIM * ODIM];
    for (int i = threadIdx.x; i < HIDDIM * ODIM; i += 256) W[i] = Wout[i];
    __syncthreads();

    int gw = (blockIdx.x * 256 + threadIdx.x) >> 5;
    int lane = threadIdx.x & 31;
    if (gw >= nRows) return;

    float4 hv = *(const float4*)(h + (size_t)gw * HIDDIM + lane * 4);
    int i0 = lane * 4;
    float acc[ODIM];
#pragma unroll
    for (int o = 0; o < ODIM; o++) {
        float s = hv.x * W[(i0 + 0) * ODIM + o];
        s = fmaf(hv.y, W[(i0 + 1) * ODIM + o], s);
        s = fmaf(hv.z, W[(i0 + 2) * ODIM + o], s);
        s = fmaf(hv.w, W[(i0 + 3) * ODIM + o], s);
        acc[o] = s;
    }
#pragma unroll
    for (int off = 16; off > 0; off >>= 1)
#pragma unroll
        for (int o = 0; o < ODIM; o++)
            acc[o] += __shfl_xor_sync(0xffffffffu, acc[o], off);

    float m = acc[0];
#pragma unroll
    for (int o = 1; o < ODIM; o++) m = fmaxf(m, acc[o]);
    float s = 0.f;
#pragma unroll
    for (int o = 0; o < ODIM; o++) s += expf(acc[o] - m);
    float lse = m + logf(s);
    if (lane < ODIM) out[(size_t)gw * ODIM + lane] = acc[lane] - lse;
}

// ---------------------------------------------------------------------------
extern "C" void kernel_launch(void* const* d_in, const int* in_sizes, int n_in,
                              void* d_out, int out_size)
{
    const float* x    = (const float*)d_in[0];
    const int*   ei   = (const int*)d_in[1];
    const float* Win  = (const float*)d_in[2];
    const float* cc   = (const float*)d_in[3];
    const float* Wout = (const float*)d_in[4];
    float* out = (float*)d_out;

    const int nE    = in_sizes[1] / 2;
    const int nRows = NNODES;

    float *h0, *h1, *C;
    int *deg, *rowStart, *cursor, *colIdx;
    cudaGetSymbolAddress((void**)&h0, g_h0);
    cudaGetSymbolAddress((void**)&h1, g_h1);
    cudaGetSymbolAddress((void**)&C,  g_C);
    cudaGetSymbolAddress((void**)&deg,      g_deg);
    cudaGetSymbolAddress((void**)&rowStart, g_rowStart);
    cudaGetSymbolAddress((void**)&cursor,   g_cursor);
    cudaGetSymbolAddress((void**)&colIdx,   g_colIdx);

    const int gemmBlocks = (nRows + 127) / 128;
    const int eBlocks    = (nE + 255) / 256;
    const int spmmBlocks = (nRows * 32 + 255) / 256;

    // --- CSR build (once per launch; reused by all 3 spmms) ---
    zero_deg_kernel<<<(nRows + 255) / 256, 256>>>(deg, nRows);
    count_kernel<<<eBlocks, 256>>>(ei, nE, deg);
    scan_kernel<<<1, 1024>>>(deg, rowStart, cursor, nRows);
    fill_kernel<<<eBlocks, 256>>>(ei, nE, cursor, colIdx);

    prep_coeffs_kernel<<<512, 256>>>(cc);

    // h0 = x @ W_in
    gemm_kernel<0><<<gemmBlocks, 256>>>(x, Win, h0, nRows, KIN);

    // h1 = A h0
    spmm_csr_kernel<<<spmmBlocks, 256>>>(rowStart, colIdx, h0, h1, nRows);

    // h0 = cheb(h1; C0)
    gemm_kernel<1><<<gemmBlocks, 256>>>(h1, C, h0, nRows, KCHEB);
    spmm_csr_kernel<<<spmmBlocks, 256>>>(rowStart, colIdx, h0, h1, nRows);

    // h0 = cheb(h1; C1)
    gemm_kernel<1><<<gemmBlocks, 256>>>(h1, C + KCHEB * HIDDIM, h0, nRows, KCHEB);
    spmm_csr_kernel<<<spmmBlocks, 256>>>(rowStart, colIdx, h0, h1, nRows);

    // out = log_softmax(h1 @ W_out)
    out_kernel<<<(nRows + 7) / 8, 256>>>(h1, Wout, out, nRows);
}

// round 4
// speedup vs baseline: 1.6762x; 1.0580x over previous
#include <cuda_runtime.h>
#include <cstdint>

#define NNODES  100000
#define HIDDIM  128
#define KIN     500
#define KCHEB   512
#define ODIM    16
#define MAXE    1600000

typedef unsigned long long u64;

// Scratch (device globals: allocation-free per harness rules)
static __device__ float g_h0[(size_t)NNODES * HIDDIM];   // 51.2 MB
static __device__ float g_h1[(size_t)NNODES * HIDDIM];   // 51.2 MB
static __device__ float g_C[2 * KCHEB * HIDDIM];         // reshaped cheb coeffs
static __device__ int   g_deg[NNODES];
static __device__ int   g_rowStart[NNODES + 1];
static __device__ int   g_cursor[NNODES];
static __device__ int   g_colIdx[MAXE];                  // 6.4 MB

// ---- packed f32x2 helpers -------------------------------------------------
__device__ __forceinline__ void fma2(u64& d, u64 a, u64 b) {
    asm("fma.rn.f32x2 %0, %1, %2, %0;" : "+l"(d) : "l"(a), "l"(b));
}
__device__ __forceinline__ u64 pk2(float x) {
    u64 r;
    asm("mov.b64 %0, {%1, %1};" : "=l"(r) : "f"(x));
    return r;
}
__device__ __forceinline__ void upk2(float& lo, float& hi, u64 v) {
    asm("mov.b64 {%0, %1}, %2;" : "=f"(lo), "=f"(hi) : "l"(v));
}

// ---------------------------------------------------------------------------
// Reshape cheb_coeffs [2,128,128,4] (l,i,o,d) -> C[l][k=4i+d][o]  ([512,128])
// ---------------------------------------------------------------------------
__global__ void prep_coeffs_kernel(const float* __restrict__ cc) {
    int idx = blockIdx.x * blockDim.x + threadIdx.x;
    if (idx >= 2 * 128 * 128 * 4) return;
    g_C[((idx >> 16) * KCHEB + ((idx >> 9) & 127) * 4 + (idx & 3)) * HIDDIM +
        ((idx >> 2) & 127)] = cc[idx];
}

// ---------------------------------------------------------------------------
// CSR build: degree histogram -> single-block scan -> scatter fill
// ---------------------------------------------------------------------------
__global__ void zero_deg_kernel(int* __restrict__ deg, int n) {
    int i = blockIdx.x * blockDim.x + threadIdx.x;
    if (i < n) deg[i] = 0;
}

__global__ void count_kernel(const int* __restrict__ ei, int nE,
                             int* __restrict__ deg) {
    int i = blockIdx.x * blockDim.x + threadIdx.x;
    if (i < nE) atomicAdd(&deg[ei[i]], 1);
}

__global__ void __launch_bounds__(1024) scan_kernel(
    const int* __restrict__ deg, int* __restrict__ rowStart,
    int* __restrict__ cursor, int n)
{
    __shared__ int s[1024];
    const int tid = threadIdx.x;
    const int CH = (n + 1023) / 1024;
    const int base = tid * CH;
    int sum = 0;
    for (int i = 0; i < CH; i++) {
        int j = base + i;
        if (j < n) sum += deg[j];
    }
    s[tid] = sum;
    __syncthreads();
    for (int off = 1; off < 1024; off <<= 1) {
        int v = (tid >= off) ? s[tid - off] : 0;
        __syncthreads();
        s[tid] += v;
        __syncthreads();
    }
    int run = (tid == 0) ? 0 : s[tid - 1];
    for (int i = 0; i < CH; i++) {
        int j = base + i;
        if (j < n) {
            rowStart[j] = run;
            cursor[j]   = run;
            run += deg[j];
        }
    }
    if (tid == 1023) rowStart[n] = run;
}

__global__ void fill_kernel(const int* __restrict__ ei, int nE,
                            int* __restrict__ cursor,
                            int* __restrict__ colIdx) {
    int i = blockIdx.x * blockDim.x + threadIdx.x;
    if (i >= nE) return;
    int row = ei[i];
    int col = ei[nE + i];
    int p = atomicAdd(&cursor[row], 1);
    colIdx[p] = col;
}

// ---------------------------------------------------------------------------
// spmm via CSR: warp per row, register accumulation, no atomics.
// ---------------------------------------------------------------------------
__global__ void __launch_bounds__(256) spmm_csr_kernel(
    const int* __restrict__ rowStart, const int* __restrict__ colIdx,
    const float* __restrict__ hin, float* __restrict__ hout, int n)
{
    int w = (blockIdx.x * 256 + threadIdx.x) >> 5;
    if (w >= n) return;
    int lane = threadIdx.x & 31;
    int s = rowStart[w];
    int e = rowStart[w + 1];

    float4 a0 = make_float4(0.f, 0.f, 0.f, 0.f);
    float4 a1 = make_float4(0.f, 0.f, 0.f, 0.f);
    int i = s;
    for (; i + 1 < e; i += 2) {
        int c0 = __ldg(&colIdx[i]);
        int c1 = __ldg(&colIdx[i + 1]);
        float4 v0 = *(const float4*)(hin + (size_t)c0 * HIDDIM + lane * 4);
        float4 v1 = *(const float4*)(hin + (size_t)c1 * HIDDIM + lane * 4);
        a0.x += v0.x; a0.y += v0.y; a0.z += v0.z; a0.w += v0.w;
        a1.x += v1.x; a1.y += v1.y; a1.z += v1.z; a1.w += v1.w;
    }
    if (i < e) {
        int c0 = __ldg(&colIdx[i]);
        float4 v0 = *(const float4*)(hin + (size_t)c0 * HIDDIM + lane * 4);
        a0.x += v0.x; a0.y += v0.y; a0.z += v0.z; a0.w += v0.w;
    }
    *(float4*)(hout + (size_t)w * HIDDIM + lane * 4) =
        make_float4(a0.x + a1.x, a0.y + a1.y, a0.z + a1.z, a0.w + a1.w);
}

// ---------------------------------------------------------------------------
// Tiled GEMM with packed fma.rn.f32x2: C[nRows,128] = A @ B.
//   CHEB=0: A is [nRows,K] row-major
//   CHEB=1: A[r, 4i+d] = T_d(tanh(h[r,i])), generated during smem fill, K=512
// Block 256 threads, tile 128x128, K-step 8, 8x8 microtile as 4 row-pairs x 8
// cols of f32x2 accumulators. A-pairs come free via 64-bit LDS (As stored
// [k][row] -> adjacent rows are adjacent floats); B duplicated via mov.b64.
// ---------------------------------------------------------------------------
template <int CHEB>
__global__ void __launch_bounds__(256) gemm_kernel(
    const float* __restrict__ A, const float* __restrict__ B,
    float* __restrict__ C, int nRows, int K)
{
    __shared__ float As[8][128];   // [k][row]
    __shared__ float Bs[8][128];   // [k][col]
    const int tid = threadIdx.x;
    const int tx  = tid & 15;      // col group (8 cols)
    const int ty  = tid >> 4;      // row group (8 rows)
    const int rowBase = blockIdx.x * 128;

    u64 acc2[4][8];                // [row-pair][col]
#pragma unroll
    for (int rp = 0; rp < 4; rp++)
#pragma unroll
        for (int c = 0; c < 8; c++) acc2[rp][c] = 0ull;

    for (int k0 = 0; k0 < K; k0 += 8) {
        // ---- A tile ----
        if (CHEB) {
            int rl = tid & 127;
            int ii = tid >> 7;
            int rg = rowBase + rl; if (rg >= nRows) rg = nRows - 1;
            int ig = (k0 >> 2) + ii;
            float t  = tanhf(A[(size_t)rg * HIDDIM + ig]);
            float T2 = fmaf(2.f * t, t, -1.f);
            float T3 = fmaf(2.f * t, T2, -t);
            As[ii * 4 + 0][rl] = 1.f;
            As[ii * 4 + 1][rl] = t;
            As[ii * 4 + 2][rl] = T2;
            As[ii * 4 + 3][rl] = T3;
        } else {
            int rl   = tid >> 1;
            int half = tid & 1;
            int rg = rowBase + rl; if (rg >= nRows) rg = nRows - 1;
            int kk = k0 + half * 4;
            float4 a = make_float4(0.f, 0.f, 0.f, 0.f);
            if (kk < K)
                a = *(const float4*)(A + (size_t)rg * K + kk);
            As[half * 4 + 0][rl] = a.x;
            As[half * 4 + 1][rl] = a.y;
            As[half * 4 + 2][rl] = a.z;
            As[half * 4 + 3][rl] = a.w;
        }
        // ---- B tile ----
        {
            int kb = tid >> 5;
            int cb = (tid & 31) << 2;
            float4 b = make_float4(0.f, 0.f, 0.f, 0.f);
            if (k0 + kb < K)
                b = *(const float4*)(B + (size_t)(k0 + kb) * HIDDIM + cb);
            *(float4*)&Bs[kb][cb] = b;
        }
        __syncthreads();

#pragma unroll
        for (int kk = 0; kk < 8; kk++) {
            // A row-pairs: 4 x u64, straight from smem (adjacent rows)
            u64 ap[4];
            ap[0] = *(const u64*)&As[kk][ty * 8 + 0];
            ap[1] = *(const u64*)&As[kk][ty * 8 + 2];
            ap[2] = *(const u64*)&As[kk][ty * 8 + 4];
            ap[3] = *(const u64*)&As[kk][ty * 8 + 6];
            float b[8];
            *(float4*)(b)     = *(const float4*)&Bs[kk][tx * 8];
            *(float4*)(b + 4) = *(const float4*)&Bs[kk][tx * 8 + 4];
#pragma unroll
            for (int c = 0; c < 8; c++) {
                u64 bb = pk2(b[c]);
#pragma unroll
                for (int rp = 0; rp < 4; rp++)
                    fma2(acc2[rp][c], ap[rp], bb);
            }
        }
        __syncthreads();
    }

    // Epilogue: unpack row-pairs, store float4s per row
#pragma unroll
    for (int rp = 0; rp < 4; rp++) {
        float lo[8], hi[8];
#pragma unroll
        for (int c = 0; c < 8; c++) upk2(lo[c], hi[c], acc2[rp][c]);
        int rg0 = rowBase + ty * 8 + rp * 2;
        if (rg0 < nRows) {
            *(float4*)(C + (size_t)rg0 * HIDDIM + tx * 8) =
                make_float4(lo[0], lo[1], lo[2], lo[3]);
            *(float4*)(C + (size_t)rg0 * HIDDIM + tx * 8 + 4) =
                make_float4(lo[4], lo[5], lo[6], lo[7]);
        }
        if (rg0 + 1 < nRows) {
            *(float4*)(C + (size_t)(rg0 + 1) * HIDDIM + tx * 8) =
                make_float4(hi[0], hi[1], hi[2], hi[3]);
            *(float4*)(C + (size_t)(rg0 + 1) * HIDDIM + tx * 8 + 4) =
                make_float4(hi[4], hi[5], hi[6], hi[7]);
        }
    }
}

// ---------------------------------------------------------------------------
// logits = h @ W_out, then log_softmax.  Warp per row.
// ---------------------------------------------------------------------------
__global__ void __launch_bounds__(256) out_kernel(
    const float* __restrict__ h, const float* __restrict__ Wout,
    float* __restrict__ out, int nRows)
{
    __shared__ float W[HIDDIM * ODIM];
    for (int i = threadIdx.x; i < HIDDIM * ODIM; i += 256) W[i] = Wout[i];
    __syncthreads();

    int gw = (blockIdx.x * 256 + threadIdx.x) >> 5;
    int lane = threadIdx.x & 31;
    if (gw >= nRows) return;

    float4 hv = *(const float4*)(h + (size_t)gw * HIDDIM + lane * 4);
    int i0 = lane * 4;
    float acc[ODIM];
#pragma unroll
    for (int o = 0; o < ODIM; o++) {
        float s = hv.x * W[(i0 + 0) * ODIM + o];
        s = fmaf(hv.y, W[(i0 + 1) * ODIM + o], s);
        s = fmaf(hv.z, W[(i0 + 2) * ODIM + o], s);
        s = fmaf(hv.w, W[(i0 + 3) * ODIM + o], s);
        acc[o] = s;
    }
#pragma unroll
    for (int off = 16; off > 0; off >>= 1)
#pragma unroll
        for (int o = 0; o < ODIM; o++)
            acc[o] += __shfl_xor_sync(0xffffffffu, acc[o], off);

    float m = acc[0];
#pragma unroll
    for (int o = 1; o < ODIM; o++) m = fmaxf(m, acc[o]);
    float s = 0.f;
#pragma unroll
    for (int o = 0; o < ODIM; o++) s += expf(acc[o] - m);
    float lse = m + logf(s);
    if (lane < ODIM) out[(size_t)gw * ODIM + lane] = acc[lane] - lse;
}

// ---------------------------------------------------------------------------
extern "C" void kernel_launch(void* const* d_in, const int* in_sizes, int n_in,
                              void* d_out, int out_size)
{
    const float* x    = (const float*)d_in[0];
    const int*   ei   = (const int*)d_in[1];
    const float* Win  = (const float*)d_in[2];
    const float* cc   = (const float*)d_in[3];
    const float* Wout = (const float*)d_in[4];
    float* out = (float*)d_out;

    const int nE    = in_sizes[1] / 2;
    const int nRows = NNODES;

    float *h0, *h1, *C;
    int *deg, *rowStart, *cursor, *colIdx;
    cudaGetSymbolAddress((void**)&h0, g_h0);
    cudaGetSymbolAddress((void**)&h1, g_h1);
    cudaGetSymbolAddress((void**)&C,  g_C);
    cudaGetSymbolAddress((void**)&deg,      g_deg);
    cudaGetSymbolAddress((void**)&rowStart, g_rowStart);
    cudaGetSymbolAddress((void**)&cursor,   g_cursor);
    cudaGetSymbolAddress((void**)&colIdx,   g_colIdx);

    const int gemmBlocks = (nRows + 127) / 128;
    const int eBlocks    = (nE + 255) / 256;
    const int spmmBlocks = (nRows * 32 + 255) / 256;

    // --- CSR build (once per launch; reused by all 3 spmms) ---
    zero_deg_kernel<<<(nRows + 255) / 256, 256>>>(deg, nRows);
    count_kernel<<<eBlocks, 256>>>(ei, nE, deg);
    scan_kernel<<<1, 1024>>>(deg, rowStart, cursor, nRows);
    fill_kernel<<<eBlocks, 256>>>(ei, nE, cursor, colIdx);

    prep_coeffs_kernel<<<512, 256>>>(cc);

    // h0 = x @ W_in
    gemm_kernel<0><<<gemmBlocks, 256>>>(x, Win, h0, nRows, KIN);

    // h1 = A h0
    spmm_csr_kernel<<<spmmBlocks, 256>>>(rowStart, colIdx, h0, h1, nRows);

    // h0 = cheb(h1; C0)
    gemm_kernel<1><<<gemmBlocks, 256>>>(h1, C, h0, nRows, KCHEB);
    spmm_csr_kernel<<<spmmBlocks, 256>>>(rowStart, colIdx, h0, h1, nRows);

    // h0 = cheb(h1; C1)
    gemm_kernel<1><<<gemmBlocks, 256>>>(h1, C + KCHEB * HIDDIM, h0, nRows, KCHEB);
    spmm_csr_kernel<<<spmmBlocks, 256>>>(rowStart, colIdx, h0, h1, nRows);

    // out = log_softmax(h1 @ W_out)
    out_kernel<<<(nRows + 7) / 8, 256>>>(h1, Wout, out, nRows);
}

// round 7
// speedup vs baseline: 3.0718x; 1.8326x over previous
#include <cuda_runtime.h>
#include <cstdint>

#define NNODES  100000
#define HIDDIM  128
#define KIN     500
#define KPAD    512
#define ODIM    16
#define MAXE    1600000

typedef unsigned long long u64;

// ---------------- device scratch (no allocations allowed) -------------------
static __device__ float    g_h0[(size_t)NNODES * HIDDIM];   // 51.2 MB
static __device__ float    g_h1[(size_t)NNODES * HIDDIM];   // 51.2 MB
static __device__ uint32_t g_Wt[KPAD * HIDDIM];             // W_in tf32, [k=512][n=128]
static __device__ uint32_t g_Ct[2 * KPAD * HIDDIM];         // cheb tf32 [l][k][o]
static __device__ int      g_deg[NNODES];
static __device__ int      g_rowStart[NNODES + 1];
static __device__ int      g_cursor[NNODES];
static __device__ int      g_colIdx[MAXE];

// ---------------- helpers ---------------------------------------------------
__device__ __forceinline__ uint32_t f2tf32(float f) {
    uint32_t r;
    asm("cvt.rna.tf32.f32 %0, %1;" : "=r"(r) : "f"(f));
    return r;
}
__device__ __forceinline__ void mma_tf32_16n8k8(float* c, const uint32_t* a,
                                                const uint32_t* b) {
    asm volatile(
        "mma.sync.aligned.m16n8k8.row.col.f32.tf32.tf32.f32 "
        "{%0,%1,%2,%3}, {%4,%5,%6,%7}, {%8,%9}, {%0,%1,%2,%3};"
        : "+f"(c[0]), "+f"(c[1]), "+f"(c[2]), "+f"(c[3])
        : "r"(a[0]), "r"(a[1]), "r"(a[2]), "r"(a[3]), "r"(b[0]), "r"(b[1]));
}

// ---------------------------------------------------------------------------
// prep: W_in [500,128] -> g_Wt [512,128] tf32 (zero pad);
//       cheb_coeffs [2,128,128,4] -> g_Ct [l][k=4i+d (512)][o=128] tf32
// ---------------------------------------------------------------------------
__global__ void prep_kernel(const float* __restrict__ Win,
                            const float* __restrict__ cc) {
    int idx = blockIdx.x * blockDim.x + threadIdx.x;
    if (idx < KPAD * HIDDIM) {
        int k = idx >> 7;
        g_Wt[idx] = (k < KIN) ? f2tf32(Win[idx]) : 0u;
        return;
    }
    idx -= KPAD * HIDDIM;
    if (idx < 2 * KPAD * HIDDIM) {
        int l = idx >> 16;
        int k = (idx >> 7) & 511;
        int o = idx & 127;
        int i = k >> 2, d = k & 3;
        g_Ct[idx] = f2tf32(cc[(((l * 128 + i) * 128) + o) * 4 + d]);
    }
}

// ---------------------------------------------------------------------------
// CSR build
// ---------------------------------------------------------------------------
__global__ void zero_deg_kernel(int* __restrict__ deg, int n) {
    int i = blockIdx.x * blockDim.x + threadIdx.x;
    if (i < n) deg[i] = 0;
}
__global__ void count_kernel(const int* __restrict__ ei, int nE,
                             int* __restrict__ deg) {
    int i = blockIdx.x * blockDim.x + threadIdx.x;
    if (i < nE) atomicAdd(&deg[ei[i]], 1);
}
__global__ void __launch_bounds__(1024) scan_kernel(
    const int* __restrict__ deg, int* __restrict__ rowStart,
    int* __restrict__ cursor, int n)
{
    __shared__ int s[1024];
    const int tid = threadIdx.x;
    const int CH = (n + 1023) / 1024;
    const int base = tid * CH;
    int sum = 0;
    for (int i = 0; i < CH; i++) {
        int j = base + i;
        if (j < n) sum += deg[j];
    }
    s[tid] = sum;
    __syncthreads();
    for (int off = 1; off < 1024; off <<= 1) {
        int v = (tid >= off) ? s[tid - off] : 0;
        __syncthreads();
        s[tid] += v;
        __syncthreads();
    }
    int run = (tid == 0) ? 0 : s[tid - 1];
    for (int i = 0; i < CH; i++) {
        int j = base + i;
        if (j < n) {
            rowStart[j] = run;
            cursor[j]   = run;
            run += deg[j];
        }
    }
    if (tid == 1023) rowStart[n] = run;
}
__global__ void fill_kernel(const int* __restrict__ ei, int nE,
                            int* __restrict__ cursor,
                            int* __restrict__ colIdx) {
    int i = blockIdx.x * blockDim.x + threadIdx.x;
    if (i >= nE) return;
    int p = atomicAdd(&cursor[ei[i]], 1);
    colIdx[p] = ei[nE + i];
}

// ---------------------------------------------------------------------------
// spmm via CSR: warp per row, register accumulation.
// ---------------------------------------------------------------------------
__global__ void __launch_bounds__(256) spmm_csr_kernel(
    const int* __restrict__ rowStart, const int* __restrict__ colIdx,
    const float* __restrict__ hin, float* __restrict__ hout, int n)
{
    int w = (blockIdx.x * 256 + threadIdx.x) >> 5;
    if (w >= n) return;
    int lane = threadIdx.x & 31;
    int s = rowStart[w];
    int e = rowStart[w + 1];

    float4 a0 = make_float4(0.f, 0.f, 0.f, 0.f);
    float4 a1 = make_float4(0.f, 0.f, 0.f, 0.f);
    int i = s;
    for (; i + 1 < e; i += 2) {
        int c0 = __ldg(&colIdx[i]);
        int c1 = __ldg(&colIdx[i + 1]);
        float4 v0 = *(const float4*)(hin + (size_t)c0 * HIDDIM + lane * 4);
        float4 v1 = *(const float4*)(hin + (size_t)c1 * HIDDIM + lane * 4);
        a0.x += v0.x; a0.y += v0.y; a0.z += v0.z; a0.w += v0.w;
        a1.x += v1.x; a1.y += v1.y; a1.z += v1.z; a1.w += v1.w;
    }
    if (i < e) {
        int c0 = __ldg(&colIdx[i]);
        float4 v0 = *(const float4*)(hin + (size_t)c0 * HIDDIM + lane * 4);
        a0.x += v0.x; a0.y += v0.y; a0.z += v0.z; a0.w += v0.w;
    }
    *(float4*)(hout + (size_t)w * HIDDIM + lane * 4) =
        make_float4(a0.x + a1.x, a0.y + a1.y, a0.z + a1.z, a0.w + a1.w);
}

// ---------------------------------------------------------------------------
// tf32 mma.sync GEMM: Cout[128-tile, 128] = A @ B  (B is [K=512][128] tf32)
//   CHEB=0: A = x [nRows, 500], zero-padded to K=512
//   CHEB=1: A[r, 4i+d] = T_d(tanh(h[r,i])), K = 512
// 8 warps as 2(m) x 4(n); warp tile 64x32; m16n8k8 atoms; K chunked by 32.
// Padded smem: As[m][k] pitch 36 words, Bs[k][n] pitch 136 words
// -> conflict-free fragment loads.
// ---------------------------------------------------------------------------
#define APITCH 36
#define BPITCH 136

template <int CHEB>
__global__ void __launch_bounds__(256) gemm_mma(
    const float* __restrict__ A, const uint32_t* __restrict__ B,
    float* __restrict__ Cout, int nRows)
{
    __shared__ uint32_t As[128 * APITCH];   // 18432 B
    __shared__ uint32_t Bs[32 * BPITCH];    // 17408 B

    const int tid  = threadIdx.x;
    const int wid  = tid >> 5;
    const int lane = tid & 31;
    const int wm = wid >> 2;          // 0..1
    const int wn = wid & 3;           // 0..3
    const int g = lane >> 2;          // group 0..7
    const int t = lane & 3;           // thread-in-group
    const int rowBase = blockIdx.x * 128;

    float acc[4][4][4];
#pragma unroll
    for (int mf = 0; mf < 4; mf++)
#pragma unroll
        for (int nf = 0; nf < 4; nf++)
#pragma unroll
            for (int r = 0; r < 4; r++) acc[mf][nf][r] = 0.f;

    for (int c = 0; c < 16; c++) {
        __syncthreads();   // previous iter's reads done before overwrite

        // ---- A tile: 128 rows x 32 k (tf32), pitch-36 layout ----
        if (CHEB) {
#pragma unroll
            for (int j = 0; j < 4; j++) {
                int pos = tid + j * 256;
                int row = pos >> 3, il = pos & 7;
                int rg = rowBase + row; if (rg >= nRows) rg = nRows - 1;
                float tv = tanhf(A[(size_t)rg * HIDDIM + c * 8 + il]);
                float T2 = fmaf(2.f * tv, tv, -1.f);
                float T3 = fmaf(2.f * tv, T2, -tv);
                uint4 q = make_uint4(f2tf32(1.f), f2tf32(tv),
                                     f2tf32(T2), f2tf32(T3));
                *(uint4*)&As[row * APITCH + il * 4] = q;
            }
        } else {
            const int kbase = c * 32;
#pragma unroll
            for (int j = 0; j < 4; j++) {
                int pos = tid + j * 256;
                int row = pos >> 3, kq = pos & 7;
                int kk = kbase + kq * 4;
                int rg = rowBase + row; if (rg >= nRows) rg = nRows - 1;
                float4 v = (kk + 4 <= KIN)
                    ? *(const float4*)(A + (size_t)rg * KIN + kk)
                    : make_float4(0.f, 0.f, 0.f, 0.f);
                uint4 q = make_uint4(f2tf32(v.x), f2tf32(v.y),
                                     f2tf32(v.z), f2tf32(v.w));
                *(uint4*)&As[row * APITCH + kq * 4] = q;
            }
        }
        // ---- B tile: 32 k-rows x 128 n (already tf32, n-contig) ----
        {
            const int kbase = c * 32;
#pragma unroll
            for (int j = 0; j < 4; j++) {
                int pos = tid + j * 256;
                int k = pos >> 5, nq = pos & 31;
                uint4 v = *(const uint4*)&B[(size_t)(kbase + k) * HIDDIM + nq * 4];
                *(uint4*)&Bs[k * BPITCH + nq * 4] = v;
            }
        }
        __syncthreads();

        // ---- 4 k-steps of m16n8k8 ----
#pragma unroll
        for (int ks = 0; ks < 4; ks++) {
            const int kk = ks * 8;
            uint32_t a[4][4], b[4][2];
#pragma unroll
            for (int mf = 0; mf < 4; mf++) {
                int mb = wm * 64 + mf * 16;
                a[mf][0] = As[(mb + g)     * APITCH + kk + t];
                a[mf][1] = As[(mb + g + 8) * APITCH + kk + t];
                a[mf][2] = As[(mb + g)     * APITCH + kk + t + 4];
                a[mf][3] = As[(mb + g + 8) * APITCH + kk + t + 4];
            }
#pragma unroll
            for (int nf = 0; nf < 4; nf++) {
                int nb = wn * 32 + nf * 8;
                b[nf][0] = Bs[(kk + t)     * BPITCH + nb + g];
                b[nf][1] = Bs[(kk + t + 4) * BPITCH + nb + g];
            }
#pragma unroll
            for (int mf = 0; mf < 4; mf++)
#pragma unroll
                for (int nf = 0; nf < 4; nf++)
                    mma_tf32_16n8k8(acc[mf][nf], a[mf], b[nf]);
        }
    }

    // ---- epilogue: c0,c1 -> (g, t*2), c2,c3 -> (g+8, t*2) ----
#pragma unroll
    for (int mf = 0; mf < 4; mf++) {
        int row0 = rowBase + wm * 64 + mf * 16 + g;
#pragma unroll
        for (int nf = 0; nf < 4; nf++) {
            int col = wn * 32 + nf * 8 + t * 2;
            if (row0 < nRows)
                *(float2*)&Cout[(size_t)row0 * HIDDIM + col] =
                    make_float2(acc[mf][nf][0], acc[mf][nf][1]);
            if (row0 + 8 < nRows)
                *(float2*)&Cout[(size_t)(row0 + 8) * HIDDIM + col] =
                    make_float2(acc[mf][nf][2], acc[mf][nf][3]);
        }
    }
}

// ---------------------------------------------------------------------------
// logits = h @ W_out, log_softmax. Warp per row.
// ---------------------------------------------------------------------------
__global__ void __launch_bounds__(256) out_kernel(
    const float* __restrict__ h, const float* __restrict__ Wout,
    float* __restrict__ out, int nRows)
{
    __shared__ float W[HIDDIM * ODIM];
    for (int i = threadIdx.x; i < HIDDIM * ODIM; i += 256) W[i] = Wout[i];
    __syncthreads();

    int gw = (blockIdx.x * 256 + threadIdx.x) >> 5;
    int lane = threadIdx.x & 31;
    if (gw >= nRows) return;

    float4 hv = *(const float4*)(h + (size_t)gw * HIDDIM + lane * 4);
    int i0 = lane * 4;
    float acc[ODIM];
#pragma unroll
    for (int o = 0; o < ODIM; o++) {
        float s = hv.x * W[(i0 + 0) * ODIM + o];
        s = fmaf(hv.y, W[(i0 + 1) * ODIM + o], s);
        s = fmaf(hv.z, W[(i0 + 2) * ODIM + o], s);
        s = fmaf(hv.w, W[(i0 + 3) * ODIM + o], s);
        acc[o] = s;
    }
#pragma unroll
    for (int off = 16; off > 0; off >>= 1)
#pragma unroll
        for (int o = 0; o < ODIM; o++)
            acc[o] += __shfl_xor_sync(0xffffffffu, acc[o], off);

    float m = acc[0];
#pragma unroll
    for (int o = 1; o < ODIM; o++) m = fmaxf(m, acc[o]);
    float s = 0.f;
#pragma unroll
    for (int o = 0; o < ODIM; o++) s += expf(acc[o] - m);
    float lse = m + logf(s);
    if (lane < ODIM) out[(size_t)gw * ODIM + lane] = acc[lane] - lse;
}

// ---------------------------------------------------------------------------
extern "C" void kernel_launch(void* const* d_in, const int* in_sizes, int n_in,
                              void* d_out, int out_size)
{
    const float* x    = (const float*)d_in[0];
    const int*   ei   = (const int*)d_in[1];
    const float* Win  = (const float*)d_in[2];
    const float* cc   = (const float*)d_in[3];
    const float* Wout = (const float*)d_in[4];
    float* out = (float*)d_out;

    const int nE    = in_sizes[1] / 2;
    const int nRows = NNODES;

    float *h0, *h1;
    uint32_t *Wt, *Ct;
    int *deg, *rowStart, *cursor, *colIdx;
    cudaGetSymbolAddress((void**)&h0, g_h0);
    cudaGetSymbolAddress((void**)&h1, g_h1);
    cudaGetSymbolAddress((void**)&Wt, g_Wt);
    cudaGetSymbolAddress((void**)&Ct, g_Ct);
    cudaGetSymbolAddress((void**)&deg,      g_deg);
    cudaGetSymbolAddress((void**)&rowStart, g_rowStart);
    cudaGetSymbolAddress((void**)&cursor,   g_cursor);
    cudaGetSymbolAddress((void**)&colIdx,   g_colIdx);

    const int gemmBlocks = (nRows + 127) / 128;          // 782
    const int eBlocks    = (nE + 255) / 256;
    const int spmmBlocks = (nRows * 32 + 255) / 256;

    // --- CSR build ---
    zero_deg_kernel<<<(nRows + 255) / 256, 256>>>(deg, nRows);
    count_kernel<<<eBlocks, 256>>>(ei, nE, deg);
    scan_kernel<<<1, 1024>>>(deg, rowStart, cursor, nRows);
    fill_kernel<<<eBlocks, 256>>>(ei, nE, cursor, colIdx);

    prep_kernel<<<(3 * KPAD * HIDDIM + 255) / 256, 256>>>(Win, cc);

    // h0 = x @ W_in  (tf32 mma.sync)
    gemm_mma<0><<<gemmBlocks, 256>>>(x, Wt, h0, nRows);
    spmm_csr_kernel<<<spmmBlocks, 256>>>(rowStart, colIdx, h0, h1, nRows);

    // h0 = cheb(h1; C0)
    gemm_mma<1><<<gemmBlocks, 256>>>(h1, Ct, h0, nRows);
    spmm_csr_kernel<<<spmmBlocks, 256>>>(rowStart, colIdx, h0, h1, nRows);

    // h0 = cheb(h1; C1)
    gemm_mma<1><<<gemmBlocks, 256>>>(h1, Ct + KPAD * HIDDIM, h0, nRows);
    spmm_csr_kernel<<<spmmBlocks, 256>>>(rowStart, colIdx, h0, h1, nRows);

    // out = log_softmax(h1 @ W_out)
    out_kernel<<<(nRows + 7) / 8, 256>>>(h1, Wout, out, nRows);
}